// round 15
// baseline (speedup 1.0000x reference)
#include <cuda_runtime.h>
#include <cstdint>

#define R        128
#define R2       (R*R)
#define R3       (R*R*R)
#define BATCH    2
#define NV       7700
#define NSURF    6890
#define NT       30000
#define EPS_W    0.001f
#define INV_R    (1.0f/128.0f)

// Scratch. Zero-initialized at module load; finalize_kernel re-zeros after
// reading, so every kernel_launch invocation (and graph replay) sees zeros.
__device__ float4  g_acc[BATCH * R3];      // 64 MB  {wsum, sem0, sem1, sem2}
__device__ uint8_t g_occ[BATCH * R3];      // 4 MB
// Per-tet precomputed data: 5 float4 per (b,t):
// [0]={a.xyz, iv} [1]={c23.xyz, packed_anchor} [2]={e1} [3]={e2} [4]={e3}
__device__ float4  g_tet[BATCH * NT * 5];  // 4.8 MB

__device__ __forceinline__ float3 ld3(const float* __restrict__ p) {
    return make_float3(p[0], p[1], p[2]);
}

// ---------------------------------------------------------------- tet setup
__global__ void tet_setup_kernel(const float* __restrict__ verts,
                                 const int*   __restrict__ tets) {
    int idx = blockIdx.x * blockDim.x + threadIdx.x;
    if (idx >= BATCH * NT) return;
    int t = idx % NT;
    int b = idx / NT;

    int i0 = tets[t * 4 + 0];
    int i1 = tets[t * 4 + 1];
    int i2 = tets[t * 4 + 2];
    int i3 = tets[t * 4 + 3];

    const float* vb = verts + (size_t)b * NV * 3;
    float3 a  = ld3(vb + (size_t)i0 * 3);
    float3 p1 = ld3(vb + (size_t)i1 * 3);
    float3 p2 = ld3(vb + (size_t)i2 * 3);
    float3 p3 = ld3(vb + (size_t)i3 * 3);

    float3 e1 = make_float3(p1.x - a.x, p1.y - a.y, p1.z - a.z);
    float3 e2 = make_float3(p2.x - a.x, p2.y - a.y, p2.z - a.z);
    float3 e3 = make_float3(p3.x - a.x, p3.y - a.y, p3.z - a.z);

    float3 c23 = make_float3(e2.y * e3.z - e2.z * e3.y,
                             e2.z * e3.x - e2.x * e3.z,
                             e2.x * e3.y - e2.y * e3.x);
    float vol6 = e1.x * c23.x + e1.y * c23.y + e1.z * c23.z;
    bool valid = fabsf(vol6) > 1e-12f;
    float iv = valid ? (1.0f / vol6) : 0.0f;

    unsigned pk;
    if (valid) {
        int ax = (int)floorf(fminf(fminf(a.x, p1.x), fminf(p2.x, p3.x)) * (float)R);
        int ay = (int)floorf(fminf(fminf(a.y, p1.y), fminf(p2.y, p3.y)) * (float)R);
        int az = (int)floorf(fminf(fminf(a.z, p1.z), fminf(p2.z, p3.z)) * (float)R);
        pk = ((unsigned)(ax & 0xFF)) | ((unsigned)(ay & 0xFF) << 8) | ((unsigned)(az & 0xFF) << 16);
    } else {
        pk = 0xFFFFFFu;  // anchor 255,255,255 -> every window voxel fails bounds
    }

    float4* o = &g_tet[(size_t)idx * 5];
    o[0] = make_float4(a.x, a.y, a.z, iv);
    o[1] = make_float4(c23.x, c23.y, c23.z, __uint_as_float(pk));
    o[2] = make_float4(e1.x, e1.y, e1.z, 0.f);
    o[3] = make_float4(e2.x, e2.y, e2.z, 0.f);
    o[4] = make_float4(e3.x, e3.y, e3.z, 0.f);
}

// ---------------------------------------------------------------- tet test
// One thread per (batch*tet, window-voxel). 125 = 5^3 window.
__global__ void tet_test_kernel() {
    int idx = blockIdx.x * blockDim.x + threadIdx.x;
    const int TOTAL = BATCH * NT * 125;
    if (idx >= TOTAL) return;

    int v  = idx % 125;
    int bt = idx / 125;
    int b  = bt / NT;

    const float4* d = &g_tet[(size_t)bt * 5];
    float4 f0 = d[0];   // a, iv
    float4 f1 = d[1];   // c23, anchor
    float4 f2 = d[2];   // e1
    float4 f3 = d[3];   // e2
    float4 f4 = d[4];   // e3

    unsigned pk = __float_as_uint(f1.w);
    int vx = (int)(pk & 0xFF)         + (v / 25);
    int vy = (int)((pk >> 8) & 0xFF)  + ((v / 5) % 5);
    int vz = (int)((pk >> 16) & 0xFF) + (v % 5);
    if ((unsigned)vx >= R || (unsigned)vy >= R || (unsigned)vz >= R) return;

    float iv = f0.w;
    float3 p = make_float3(((float)vx + 0.5f) * INV_R - f0.x,
                           ((float)vy + 0.5f) * INV_R - f0.y,
                           ((float)vz + 0.5f) * INV_R - f0.z);

    float l1 = (p.x * f1.x + p.y * f1.y + p.z * f1.z) * iv;

    // (p x e3) . e1
    float l2 = ((p.y * f4.z - p.z * f4.y) * f2.x +
                (p.z * f4.x - p.x * f4.z) * f2.y +
                (p.x * f4.y - p.y * f4.x) * f2.z) * iv;

    // (e2 x p) . e1
    float l3 = ((f3.y * p.z - f3.z * p.y) * f2.x +
                (f3.z * p.x - f3.x * p.z) * f2.y +
                (f3.x * p.y - f3.y * p.x) * f2.z) * iv;

    if (l1 >= 0.f && l2 >= 0.f && l3 >= 0.f && (l1 + l2 + l3) <= 1.0f) {
        int lin = ((b * R + vz) * R + vy) * R + vx;
        g_occ[lin] = 1;   // scatter-max of {0,1} -> plain store
    }
}

// ---------------------------------------------------------------- splat
// One WARP per (batch, surface-vertex). Separable Gaussian: w = wx*wy*wz.
__global__ void splat_kernel(const float* __restrict__ verts,
                             const float* __restrict__ code) {
    int gw   = (blockIdx.x * blockDim.x + threadIdx.x) >> 5;
    int lane = threadIdx.x & 31;
    if (gw >= BATCH * NSURF) return;
    int s = gw % NSURF;
    int b = gw / NSURF;

    float3 vs = ld3(verts + ((size_t)b * NV + s) * 3);
    float3 vc = ld3(code  + ((size_t)b * NSURF + s) * 3);

    int bx = (int)floorf(vs.x * (float)R);
    int by = (int)floorf(vs.y * (float)R);
    int bz = (int)floorf(vs.z * (float)R);

    // lanes 0-6: wx[0..6], lanes 7-13: wy, lanes 14-20: wz
    float d = 0.f;
    if (lane < 7)        d = ((float)(bx + lane      - 3) + 0.5f) * INV_R - vs.x;
    else if (lane < 14)  d = ((float)(by + (lane-7)  - 3) + 0.5f) * INV_R - vs.y;
    else if (lane < 21)  d = ((float)(bz + (lane-14) - 3) + 0.5f) * INV_R - vs.z;
    float wd = __expf(-d * d * 200.0f);   // 1/(2*sigma^2), sigma=0.05

    #pragma unroll
    for (int base = 0; base < 343; base += 32) {
        int o  = base + lane;
        int oc = (o < 343) ? o : 342;     // clamp so shuffle idx is sane
        int i = oc / 49;
        int j = (oc / 7) % 7;
        int k = oc % 7;
        float wx = __shfl_sync(0xffffffffu, wd, i);
        float wy = __shfl_sync(0xffffffffu, wd, j + 7);
        float wz = __shfl_sync(0xffffffffu, wd, k + 14);

        int vx = bx + i - 3;
        int vy = by + j - 3;
        int vz = bz + k - 3;
        bool ok = (o < 343) &&
                  (unsigned)vx < R && (unsigned)vy < R && (unsigned)vz < R;
        if (ok) {
            float w = wx * wy * wz;
            int lin = ((b * R + vz) * R + vy) * R + vx;
            float4* ptr = &g_acc[lin];
            asm volatile("red.global.add.v4.f32 [%0], {%1, %2, %3, %4};"
                         :: "l"(ptr), "f"(w), "f"(w * vc.x), "f"(w * vc.y), "f"(w * vc.z)
                         : "memory");
        }
    }
}

// ---------------------------------------------------------------- finalize
// One voxel per thread (fully coalesced: float4 at 16B/lane). Reads scratch,
// writes output, RE-ZEROS scratch so the next graph replay starts clean.
// out layout: (B, 3, Z, Y, X); lin-within-batch is already z*R2 + y*R + x.
__global__ void finalize_kernel(float* __restrict__ out) {
    int i = blockIdx.x * blockDim.x + threadIdx.x;
    if (i >= BATCH * R3) return;
    int b = i / R3;
    int l = i - b * R3;

    float4 acc = g_acc[i];
    float  occ = (float)g_occ[i];

    // Re-zero scratch (coalesced; lines L2-resident from the reads above).
    g_acc[i] = make_float4(0.f, 0.f, 0.f, 0.f);
    g_occ[i] = 0;

    float sc = occ / (acc.x + EPS_W);   // occ in {0,1}

    float* ob = out + (size_t)b * 3 * R3 + l;
    ob[0]      = acc.y * sc;
    ob[R3]     = acc.z * sc;
    ob[2 * R3] = acc.w * sc;
}

extern "C" void kernel_launch(void* const* d_in, const int* in_sizes, int n_in,
                              void* d_out, int out_size) {
    const float* verts = (const float*)d_in[0];   // smpl_vertices (B, NV, 3)
    const float* code  = (const float*)d_in[1];   // vertex_code   (B, NSURF, 3)
    // d_in[2] face_indices: unused (dead code in reference)
    const int*   tets  = (const int*)d_in[3];     // tet_indices   (NT, 4)
    float*       out   = (float*)d_out;

    const int T = 256;
    tet_setup_kernel<<<(BATCH * NT + T - 1) / T, T>>>(verts, tets);
    tet_test_kernel<<<(BATCH * NT * 125 + T - 1) / T, T>>>();
    splat_kernel<<<(BATCH * NSURF * 32 + T - 1) / T, T>>>(verts, code);
    finalize_kernel<<<(BATCH * R3 + T - 1) / T, T>>>(out);
}

// round 16
// speedup vs baseline: 2.3131x; 2.3131x over previous
#include <cuda_runtime.h>
#include <cstdint>

#define R        128
#define R2       (R*R)
#define R3       (R*R*R)
#define BATCH    2
#define NV       7700
#define NSURF    6890
#define NT       30000
#define EPS_W    0.001f
#define INV_R    (1.0f/128.0f)

// Scratch: zeroed by K1 at the start of every launch.
__device__ float4  g_acc[BATCH * R3];      // 64 MB  {wsum, sem0, sem1, sem2}
__device__ uint8_t g_occ[BATCH * R3];      // 4 MB
// Per-tet precomputed: [0]={a,iv} [1]={c23,anchor} [2]={e1} [3]={e2} [4]={e3}
__device__ float4  g_tet[BATCH * NT * 5];  // 4.8 MB

__device__ __forceinline__ float3 ld3(const float* __restrict__ p) {
    return make_float3(p[0], p[1], p[2]);
}

// ---------------------------------------------------------------- K1: setup + zero
// Block layout: [0,NS) tet_setup | [NS, NS+NZA) zero g_acc | rest zero g_occ.
#define K1_NS   ((BATCH * NT + 255) / 256)            // 235
#define K1_NZA  (BATCH * R3 / 256)                    // 16384 (float4 each)
#define K1_NZO  (BATCH * R3 / 16 / 256)               // 1024  (uint4 each)
#define K1_GRID (K1_NS + K1_NZA + K1_NZO)

__global__ void k1_setup_zero_kernel(const float* __restrict__ verts,
                                     const int*   __restrict__ tets) {
    int blk = blockIdx.x;
    int tid = threadIdx.x;

    if (blk >= K1_NS) {
        if (blk < K1_NS + K1_NZA) {
            int i = (blk - K1_NS) * 256 + tid;
            g_acc[i] = make_float4(0.f, 0.f, 0.f, 0.f);
        } else {
            int i = (blk - K1_NS - K1_NZA) * 256 + tid;
            reinterpret_cast<uint4*>(g_occ)[i] = make_uint4(0u, 0u, 0u, 0u);
        }
        return;
    }

    int idx = blk * 256 + tid;
    if (idx >= BATCH * NT) return;
    int t = idx % NT;
    int b = idx / NT;

    int i0 = tets[t * 4 + 0];
    int i1 = tets[t * 4 + 1];
    int i2 = tets[t * 4 + 2];
    int i3 = tets[t * 4 + 3];

    const float* vb = verts + (size_t)b * NV * 3;
    float3 a  = ld3(vb + (size_t)i0 * 3);
    float3 p1 = ld3(vb + (size_t)i1 * 3);
    float3 p2 = ld3(vb + (size_t)i2 * 3);
    float3 p3 = ld3(vb + (size_t)i3 * 3);

    float3 e1 = make_float3(p1.x - a.x, p1.y - a.y, p1.z - a.z);
    float3 e2 = make_float3(p2.x - a.x, p2.y - a.y, p2.z - a.z);
    float3 e3 = make_float3(p3.x - a.x, p3.y - a.y, p3.z - a.z);

    float3 c23 = make_float3(e2.y * e3.z - e2.z * e3.y,
                             e2.z * e3.x - e2.x * e3.z,
                             e2.x * e3.y - e2.y * e3.x);
    float vol6 = e1.x * c23.x + e1.y * c23.y + e1.z * c23.z;
    bool valid = fabsf(vol6) > 1e-12f;
    float iv = valid ? (1.0f / vol6) : 0.0f;

    unsigned pk;
    if (valid) {
        int ax = (int)floorf(fminf(fminf(a.x, p1.x), fminf(p2.x, p3.x)) * (float)R);
        int ay = (int)floorf(fminf(fminf(a.y, p1.y), fminf(p2.y, p3.y)) * (float)R);
        int az = (int)floorf(fminf(fminf(a.z, p1.z), fminf(p2.z, p3.z)) * (float)R);
        pk = ((unsigned)(ax & 0xFF)) | ((unsigned)(ay & 0xFF) << 8) | ((unsigned)(az & 0xFF) << 16);
    } else {
        pk = 0xFFFFFFu;  // anchor 255,255,255 -> every window voxel fails bounds
    }

    float4* o = &g_tet[(size_t)idx * 5];
    o[0] = make_float4(a.x, a.y, a.z, iv);
    o[1] = make_float4(c23.x, c23.y, c23.z, __uint_as_float(pk));
    o[2] = make_float4(e1.x, e1.y, e1.z, 0.f);
    o[3] = make_float4(e2.x, e2.y, e2.z, 0.f);
    o[4] = make_float4(e3.x, e3.y, e3.z, 0.f);
}

// ---------------------------------------------------------------- K2: splat + tet test
// Block layout: [0,NSPLAT) splat (long-latency atomics, start first) | rest test.
#define K2_NSPLAT ((BATCH * NSURF * 32 + 255) / 256)      // 1723
#define K2_NTEST  ((BATCH * NT * 125 + 255) / 256)        // 29297
#define K2_GRID   (K2_NSPLAT + K2_NTEST)

__global__ void k2_splat_test_kernel(const float* __restrict__ verts,
                                     const float* __restrict__ code) {
    int blk = blockIdx.x;
    int tid = threadIdx.x;

    if (blk < K2_NSPLAT) {
        // ---- splat: one warp per (batch, surface-vertex), separable Gaussian
        int gw   = (blk * 256 + tid) >> 5;
        int lane = tid & 31;
        if (gw >= BATCH * NSURF) return;
        int s = gw % NSURF;
        int b = gw / NSURF;

        float3 vs = ld3(verts + ((size_t)b * NV + s) * 3);
        float3 vc = ld3(code  + ((size_t)b * NSURF + s) * 3);

        int bx = (int)floorf(vs.x * (float)R);
        int by = (int)floorf(vs.y * (float)R);
        int bz = (int)floorf(vs.z * (float)R);

        // lanes 0-6: wx, 7-13: wy, 14-20: wz
        float d = 0.f;
        if (lane < 7)        d = ((float)(bx + lane      - 3) + 0.5f) * INV_R - vs.x;
        else if (lane < 14)  d = ((float)(by + (lane-7)  - 3) + 0.5f) * INV_R - vs.y;
        else if (lane < 21)  d = ((float)(bz + (lane-14) - 3) + 0.5f) * INV_R - vs.z;
        float wd = __expf(-d * d * 200.0f);   // 1/(2*sigma^2), sigma=0.05

        #pragma unroll
        for (int base = 0; base < 343; base += 32) {
            int o  = base + lane;
            int oc = (o < 343) ? o : 342;
            int i = oc / 49;
            int j = (oc / 7) % 7;
            int k = oc % 7;
            float wx = __shfl_sync(0xffffffffu, wd, i);
            float wy = __shfl_sync(0xffffffffu, wd, j + 7);
            float wz = __shfl_sync(0xffffffffu, wd, k + 14);

            int vx = bx + i - 3;
            int vy = by + j - 3;
            int vz = bz + k - 3;
            bool ok = (o < 343) &&
                      (unsigned)vx < R && (unsigned)vy < R && (unsigned)vz < R;
            if (ok) {
                float w = wx * wy * wz;
                int lin = ((b * R + vz) * R + vy) * R + vx;
                float4* ptr = &g_acc[lin];
                asm volatile("red.global.add.v4.f32 [%0], {%1, %2, %3, %4};"
                             :: "l"(ptr), "f"(w), "f"(w * vc.x), "f"(w * vc.y), "f"(w * vc.z)
                             : "memory");
            }
        }
        return;
    }

    // ---- tet test: one thread per (batch*tet, window-voxel), 125 = 5^3
    int idx = (blk - K2_NSPLAT) * 256 + tid;
    if (idx >= BATCH * NT * 125) return;

    int v  = idx % 125;
    int bt = idx / 125;
    int b  = bt / NT;

    const float4* dd = &g_tet[(size_t)bt * 5];
    float4 f0 = dd[0];   // a, iv
    float4 f1 = dd[1];   // c23, anchor
    float4 f2 = dd[2];   // e1
    float4 f3 = dd[3];   // e2
    float4 f4 = dd[4];   // e3

    unsigned pk = __float_as_uint(f1.w);
    int vx = (int)(pk & 0xFF)         + (v / 25);
    int vy = (int)((pk >> 8) & 0xFF)  + ((v / 5) % 5);
    int vz = (int)((pk >> 16) & 0xFF) + (v % 5);
    if ((unsigned)vx >= R || (unsigned)vy >= R || (unsigned)vz >= R) return;

    float iv = f0.w;
    float3 p = make_float3(((float)vx + 0.5f) * INV_R - f0.x,
                           ((float)vy + 0.5f) * INV_R - f0.y,
                           ((float)vz + 0.5f) * INV_R - f0.z);

    float l1 = (p.x * f1.x + p.y * f1.y + p.z * f1.z) * iv;

    float l2 = ((p.y * f4.z - p.z * f4.y) * f2.x +
                (p.z * f4.x - p.x * f4.z) * f2.y +
                (p.x * f4.y - p.y * f4.x) * f2.z) * iv;

    float l3 = ((f3.y * p.z - f3.z * p.y) * f2.x +
                (f3.z * p.x - f3.x * p.z) * f2.y +
                (f3.x * p.y - f3.y * p.x) * f2.z) * iv;

    if (l1 >= 0.f && l2 >= 0.f && l3 >= 0.f && (l1 + l2 + l3) <= 1.0f) {
        int lin = ((b * R + vz) * R + vy) * R + vx;
        g_occ[lin] = 1;   // scatter-max of {0,1} -> plain store
    }
}

// ---------------------------------------------------------------- K3: finalize
// One voxel per thread, pure read + output write (R12 structure).
// out layout: (B, 3, Z, Y, X); lin-within-batch is already z*R2 + y*R + x.
__global__ void finalize_kernel(float* __restrict__ out) {
    int i = blockIdx.x * blockDim.x + threadIdx.x;
    if (i >= BATCH * R3) return;
    int b = i / R3;
    int l = i - b * R3;

    float4 acc = g_acc[i];
    float  occ = (float)g_occ[i];
    float  sc  = occ / (acc.x + EPS_W);   // occ in {0,1}

    float* ob = out + (size_t)b * 3 * R3 + l;
    ob[0]      = acc.y * sc;
    ob[R3]     = acc.z * sc;
    ob[2 * R3] = acc.w * sc;
}

extern "C" void kernel_launch(void* const* d_in, const int* in_sizes, int n_in,
                              void* d_out, int out_size) {
    const float* verts = (const float*)d_in[0];   // smpl_vertices (B, NV, 3)
    const float* code  = (const float*)d_in[1];   // vertex_code   (B, NSURF, 3)
    // d_in[2] face_indices: unused (dead code in reference)
    const int*   tets  = (const int*)d_in[3];     // tet_indices   (NT, 4)
    float*       out   = (float*)d_out;

    k1_setup_zero_kernel<<<K1_GRID, 256>>>(verts, tets);
    k2_splat_test_kernel<<<K2_GRID, 256>>>(verts, code);
    finalize_kernel<<<(BATCH * R3 + 255) / 256, 256>>>(out);
}